// round 15
// baseline (speedup 1.0000x reference)
#include <cuda_runtime.h>
#include <cuda_bf16.h>
#include <math.h>
#include <stdint.h>

#define NN 100000
#define NE 1600000
#define NG 64
#define FD 50
#define KPP 672       // padded K: 21 chunks of 32
#define KSTEP 32
#define NSTEP 21
#define NL 3
#define CN 64         // GEMM N (cols 50..63 zero)
#define ASTR 40       // smem row stride in bf16 units (32 + 8 pad)

// ---------------- static scratch ----------------
__device__ int    g_deg[NN];
__device__ int    g_rowptr[NN + 1];
__device__ int    g_cursor[NN];
__device__ int    g_col[NE];
__device__ float  g_dinv[NN];
__device__ float  g_amp[NN];
__device__ float  g_att[NN];
__device__ double g_avg;
__device__ float  g_ax[2 * NN];
__device__ float  g_h[NN * FD];
__device__ float  g_h2[NN * FD];
__device__ float  g_base[NN * FD];
__device__ float  g_y[NN * FD];
__device__ __align__(16) __nv_bfloat16 g_extH[(size_t)NN * KPP];  // ~134MB
__device__ __align__(16) __nv_bfloat16 g_extL[(size_t)NN * KPP];  // ~134MB
__device__ __align__(16) __nv_bfloat16 g_CH[NL * CN * KPP];
__device__ __align__(16) __nv_bfloat16 g_CL[NL * CN * KPP];
__device__ double g_bns[2 * CN];
__device__ float  g_scale[CN];
__device__ float  g_shift[CN];
__device__ float  g_gr[NG * FD];

// ---------------- helpers ----------------
__device__ __forceinline__ uint32_t smem_u32(const void* p) {
    uint32_t a;
    asm("{ .reg .u64 t; cvta.to.shared.u64 t, %1; cvt.u32.u64 %0, t; }" : "=r"(a) : "l"(p));
    return a;
}
__device__ __forceinline__ void ldsm4(uint32_t* r, uint32_t a) {
    asm volatile("ldmatrix.sync.aligned.m8n8.x4.shared.b16 {%0,%1,%2,%3}, [%4];"
        : "=r"(r[0]), "=r"(r[1]), "=r"(r[2]), "=r"(r[3]) : "r"(a));
}
__device__ __forceinline__ void mma_bf16(float* d, const uint32_t* a, const uint32_t* b) {
    asm volatile("mma.sync.aligned.m16n8k16.row.col.f32.bf16.bf16.f32 "
        "{%0,%1,%2,%3}, {%4,%5,%6,%7}, {%8,%9}, {%0,%1,%2,%3};"
        : "+f"(d[0]), "+f"(d[1]), "+f"(d[2]), "+f"(d[3])
        : "r"(a[0]), "r"(a[1]), "r"(a[2]), "r"(a[3]), "r"(b[0]), "r"(b[1]));
}
__device__ __forceinline__ void bsplit(float v, __nv_bfloat16* H, __nv_bfloat16* L, size_t i) {
    __nv_bfloat16 h = __float2bfloat16(v);
    H[i] = h;
    L[i] = __float2bfloat16(v - __bfloat162float(h));
}

// ---------------- setup kernels ----------------
__global__ void __launch_bounds__(256) k_zero0() {
    int i = blockIdx.x * 256 + threadIdx.x;
    if (i < NN) g_deg[i] = 0;
    if (i == 0) g_avg = 0.0;
}

__global__ void __launch_bounds__(256) k_hist(const int* __restrict__ dst) {
    int e = blockIdx.x * 256 + threadIdx.x;
    if (e < NE) atomicAdd(&g_deg[dst[e]], 1);
}

#define SCAN_T 1024
#define SCAN_CHUNK 98
__global__ void __launch_bounds__(SCAN_T) k_scan() {
    __shared__ int part[SCAN_T];
    int t = threadIdx.x;
    int st = t * SCAN_CHUNK;
    int s = 0;
    for (int i = 0; i < SCAN_CHUNK; i++) {
        int idx = st + i;
        if (idx < NN) s += g_deg[idx];
    }
    part[t] = s;
    __syncthreads();
    for (int off = 1; off < SCAN_T; off <<= 1) {
        int v = 0;
        if (t >= off) v = part[t - off];
        __syncthreads();
        part[t] += v;
        __syncthreads();
    }
    int run = part[t] - s;
    for (int i = 0; i < SCAN_CHUNK; i++) {
        int idx = st + i;
        if (idx < NN) { g_rowptr[idx] = run; run += g_deg[idx]; }
    }
    if (t == SCAN_T - 1) g_rowptr[NN] = part[SCAN_T - 1];
}

__global__ void __launch_bounds__(256) k_dinv() {
    int v = blockIdx.x * 256 + threadIdx.x;
    float lg = 0.f;
    if (v < NN) {
        int d = g_deg[v];
        g_dinv[v] = rsqrtf((float)(d + 1));
        g_cursor[v] = g_rowptr[v];
        lg = log1pf((float)d);
    }
    for (int o = 16; o; o >>= 1) lg += __shfl_down_sync(0xffffffffu, lg, o);
    __shared__ float ws[8];
    int w = threadIdx.x >> 5, ln = threadIdx.x & 31;
    if (ln == 0) ws[w] = lg;
    __syncthreads();
    if (threadIdx.x == 0) {
        float tt = 0.f;
        for (int i = 0; i < 8; i++) tt += ws[i];
        atomicAdd(&g_avg, (double)tt);
    }
}

__global__ void __launch_bounds__(256) k_scatter(const int* __restrict__ src,
                                                 const int* __restrict__ dst) {
    int e = blockIdx.x * 256 + threadIdx.x;
    if (e < NE) {
        int d = dst[e];
        int p = atomicAdd(&g_cursor[d], 1);
        g_col[p] = src[e];
    }
}

__global__ void __launch_bounds__(256) k_amp() {
    int v = blockIdx.x * 256 + threadIdx.x;
    if (v < NN) {
        float avgl = (float)(g_avg / (double)NN);
        int d = g_deg[v];
        float dc = fmaxf((float)d, 1.f);
        float lg = log1pf(dc);
        g_amp[v] = lg / avgl;
        g_att[v] = avgl / lg;
    }
}

// GCN linearity: ax_v = dinv_v * (dinv_v*x_v + sum_u dinv_u*x_u); unroll-4 prefetch
__global__ void __launch_bounds__(256) k_gcnagg(const float* __restrict__ x) {
    int v = blockIdx.x * 256 + threadIdx.x;
    if (v >= NN) return;
    const float2* xv = (const float2*)x;
    int r0 = g_rowptr[v], r1 = g_rowptr[v + 1];
    float dv = g_dinv[v];
    float2 xs = xv[v];
    float a0 = dv * xs.x, a1 = dv * xs.y;
    int i = r0;
    for (; i + 4 <= r1; i += 4) {
        int u0 = g_col[i], u1 = g_col[i + 1], u2 = g_col[i + 2], u3 = g_col[i + 3];
        float d0 = g_dinv[u0], d1 = g_dinv[u1], d2 = g_dinv[u2], d3 = g_dinv[u3];
        float2 x0 = xv[u0], x1 = xv[u1], x2 = xv[u2], x3 = xv[u3];
        a0 += d0 * x0.x + d1 * x1.x + d2 * x2.x + d3 * x3.x;
        a1 += d0 * x0.y + d1 * x1.y + d2 * x2.y + d3 * x3.y;
    }
    for (; i < r1; i++) {
        int u = g_col[i];
        float du = g_dinv[u];
        float2 xu = xv[u];
        a0 += du * xu.x;
        a1 += du * xu.y;
    }
    g_ax[2 * v] = dv * a0;
    g_ax[2 * v + 1] = dv * a1;
}

__global__ void __launch_bounds__(256) k_gcnmm(const float* __restrict__ Wg,
                                               const float* __restrict__ bg) {
    int idx = blockIdx.x * 256 + threadIdx.x;
    if (idx < NN * FD) {
        int v = idx / FD;
        int f = idx - v * FD;
        g_h[idx] = g_ax[2 * v] * Wg[f] + g_ax[2 * v + 1] * Wg[FD + f] + bg[f];
    }
}

// ---------------- combined weights -> bf16 hi/lo, layout [l][n][k] ----------------
__global__ void __launch_bounds__(256) k_combW(const float* __restrict__ postW,
                                               const float* __restrict__ linW) {
    int idx = blockIdx.x * 256 + threadIdx.x;
    if (idx >= NL * CN * KPP) return;
    int l = idx / (CN * KPP);
    int r = idx - l * (CN * KPP);
    int n = r / KPP;
    int k = r - n * KPP;
    float v = 0.f;
    if (k < 650 && n < FD) {
        const float* wq = postW + ((size_t)l * 650 + k) * FD;
        const float* wl = linW + (size_t)l * FD * FD;
        #pragma unroll 10
        for (int j = 0; j < FD; j++) v += wq[j] * wl[j * FD + n];
    }
    bsplit(v, g_CH, g_CL, idx);
}

// ---------------- per-layer kernels ----------------
__global__ void __launch_bounds__(256) kA(int l, const float* __restrict__ preW,
                                          const float* __restrict__ preb) {
    __shared__ float shW[100 * FD];
    __shared__ float shH[4][FD];
    int tid = threadIdx.x;
    const float* Wp = preW + (size_t)l * 100 * FD;
    for (int i = tid; i < 100 * FD; i += 256) shW[i] = Wp[i];
    int grp = tid >> 6, f = tid & 63;
    int v = blockIdx.x * 4 + grp;
    if (f < FD) shH[grp][f] = g_h[(size_t)v * FD + f];
    __syncthreads();
    if (f < FD) {
        float b = preb[l * FD + f];
        float yv = 0.f;
        #pragma unroll 10
        for (int k = 0; k < FD; k++) {
            float hv = shH[grp][k];
            b  += hv * shW[k * FD + f];
            yv += hv * shW[(FD + k) * FD + f];
        }
        g_base[(size_t)v * FD + f] = b;
        g_y[(size_t)v * FD + f] = yv;
    }
}

// kB: edge aggregation with unroll-4 MLP prefetch; writes full 650-wide ext hi/lo
__global__ void __launch_bounds__(256) kB() {
    int tid = threadIdx.x;
    int grp = tid >> 6, f = tid & 63;
    int v = blockIdx.x * 4 + grp;
    __nv_bfloat16* eh = g_extH + (size_t)v * KPP;
    __nv_bfloat16* el = g_extL + (size_t)v * KPP;
    if (f >= FD) {
        __nv_bfloat16 z = __float2bfloat16(0.f);
        for (int p = 650 + (f - FD); p < KPP; p += 14) {
            eh[p] = z;
            el[p] = z;
        }
        return;
    }
    float base = g_base[(size_t)v * FD + f];
    int r0 = g_rowptr[v], r1 = g_rowptr[v + 1];
    float s = 0.f, ss = 0.f, mn = INFINITY, mx = -INFINITY;
    int i = r0;
    for (; i + 4 <= r1; i += 4) {
        int u0 = g_col[i], u1 = g_col[i + 1], u2 = g_col[i + 2], u3 = g_col[i + 3];
        float h0 = base + g_y[(size_t)u0 * FD + f];
        float h1 = base + g_y[(size_t)u1 * FD + f];
        float h2 = base + g_y[(size_t)u2 * FD + f];
        float h3 = base + g_y[(size_t)u3 * FD + f];
        s += (h0 + h1) + (h2 + h3);
        ss += (h0 * h0 + h1 * h1) + (h2 * h2 + h3 * h3);
        mn = fminf(mn, fminf(fminf(h0, h1), fminf(h2, h3)));
        mx = fmaxf(mx, fmaxf(fmaxf(h0, h1), fmaxf(h2, h3)));
    }
    for (; i < r1; i++) {
        int u = g_col[i];
        float h = base + g_y[(size_t)u * FD + f];
        s += h; ss += h * h;
        mn = fminf(mn, h); mx = fmaxf(mx, h);
    }
    int deg = r1 - r0;
    float dc = fmaxf((float)deg, 1.f);
    float mean = s / dc;
    float msq = ss / dc;
    float var = fmaxf(msq - mean * mean, 0.f);
    float sd = sqrtf(var + 1e-5f);
    if (deg == 0) { mn = 0.f; mx = 0.f; }
    float am = g_amp[v], at = g_att[v];
    bsplit(g_h[(size_t)v * FD + f], eh, el, f);
    bsplit(mean,      eh, el, 50 + f);
    bsplit(mn,        eh, el, 100 + f);
    bsplit(mx,        eh, el, 150 + f);
    bsplit(sd,        eh, el, 200 + f);
    bsplit(am * mean, eh, el, 250 + f);
    bsplit(am * mn,   eh, el, 300 + f);
    bsplit(am * mx,   eh, el, 350 + f);
    bsplit(am * sd,   eh, el, 400 + f);
    bsplit(at * mean, eh, el, 450 + f);
    bsplit(at * mn,   eh, el, 500 + f);
    bsplit(at * mx,   eh, el, 550 + f);
    bsplit(at * sd,   eh, el, 600 + f);
}

__global__ void __launch_bounds__(128) k_zero_bn() {
    int i = threadIdx.x;
    if (i < 2 * CN) g_bns[i] = 0.0;
}

// ---------------- mma.sync GEMM (R8 tiling, unchanged) ----------------
__global__ void __launch_bounds__(256) kC_mma(int l) {
    __shared__ __align__(16) __nv_bfloat16 sAh[128 * ASTR];
    __shared__ __align__(16) __nv_bfloat16 sAl[128 * ASTR];
    __shared__ __align__(16) __nv_bfloat16 sBh[64 * ASTR];
    __shared__ __align__(16) __nv_bfloat16 sBl[64 * ASTR];
    int tid = threadIdx.x, lane = tid & 31, wid = tid >> 5;
    int wm = wid & 3, wn = wid >> 2;
    int v0 = blockIdx.x * 128;

    float acc[2][4][4] = {};

    uint32_t bAh = smem_u32(sAh), bAl = smem_u32(sAl);
    uint32_t bBh = smem_u32(sBh), bBl = smem_u32(sBl);
    int lr = lane & 15, lh = lane >> 4;
    int bgrp = lane >> 3, bli = lane & 7;

    for (int s = 0; s < NSTEP; s++) {
        int k0 = s * KSTEP;
        __syncthreads();
        #pragma unroll
        for (int t = 0; t < 2; t++) {
            int c = tid + 256 * t;
            int r = c >> 2, q = c & 3;
            int v = v0 + r;
            uint4 h4 = make_uint4(0, 0, 0, 0), l4 = h4;
            if (v < NN) {
                const uint4* ph = (const uint4*)(g_extH + (size_t)v * KPP + k0);
                const uint4* pl = (const uint4*)(g_extL + (size_t)v * KPP + k0);
                h4 = ph[q]; l4 = pl[q];
            }
            *(uint4*)(sAh + r * ASTR + q * 8) = h4;
            *(uint4*)(sAl + r * ASTR + q * 8) = l4;
        }
        {
            int n = tid >> 2, q = tid & 3;
            const uint4* ph = (const uint4*)(g_CH + ((size_t)l * CN + n) * KPP + k0);
            const uint4* pl = (const uint4*)(g_CL + ((size_t)l * CN + n) * KPP + k0);
            *(uint4*)(sBh + n * ASTR + q * 8) = ph[q];
            *(uint4*)(sBl + n * ASTR + q * 8) = pl[q];
        }
        __syncthreads();

        #pragma unroll
        for (int kk = 0; kk < 2; kk++) {
            uint32_t ah[2][4], al[2][4], bh[4][2], bl[4][2];
            #pragma unroll
            for (int im = 0; im < 2; im++) {
                uint32_t off = (uint32_t)(((wm * 32 + im * 16 + lr) * ASTR + kk * 16 + lh * 8) * 2);
                ldsm4(ah[im], bAh + off);
                ldsm4(al[im], bAl + off);
            }
            #pragma unroll
            for (int jg = 0; jg < 2; jg++) {
                uint32_t off = (uint32_t)(((wn * 32 + jg * 16 + (bgrp >> 1) * 8 + bli) * ASTR
                                           + kk * 16 + (bgrp & 1) * 8) * 2);
                uint32_t r4[4];
                ldsm4(r4, bBh + off);
                bh[jg * 2][0] = r4[0]; bh[jg * 2][1] = r4[1];
                bh[jg * 2 + 1][0] = r4[2]; bh[jg * 2 + 1][1] = r4[3];
                ldsm4(r4, bBl + off);
                bl[jg * 2][0] = r4[0]; bl[jg * 2][1] = r4[1];
                bl[jg * 2 + 1][0] = r4[2]; bl[jg * 2 + 1][1] = r4[3];
            }
            #pragma unroll
            for (int im = 0; im < 2; im++)
                #pragma unroll
                for (int jn = 0; jn < 4; jn++) {
                    mma_bf16(acc[im][jn], ah[im], bh[jn]);
                    mma_bf16(acc[im][jn], ah[im], bl[jn]);
                    mma_bf16(acc[im][jn], al[im], bh[jn]);
                }
        }
    }

    #pragma unroll
    for (int im = 0; im < 2; im++) {
        int r0 = v0 + wm * 32 + im * 16 + (lane >> 2);
        #pragma unroll
        for (int jn = 0; jn < 4; jn++) {
            int cb = wn * 32 + jn * 8 + (lane & 3) * 2;
            if (cb < FD) {
                if (r0 < NN)
                    *(float2*)&g_h2[(size_t)r0 * FD + cb] =
                        make_float2(acc[im][jn][0], acc[im][jn][1]);
                if (r0 + 8 < NN)
                    *(float2*)&g_h2[(size_t)(r0 + 8) * FD + cb] =
                        make_float2(acc[im][jn][2], acc[im][jn][3]);
            }
        }
    }
}

__global__ void __launch_bounds__(64) k_bnstat() {
    int f = threadIdx.x;
    if (f >= FD) return;
    int v0 = blockIdx.x * 256;
    int ve = min(v0 + 256, NN);
    float s = 0.f, q = 0.f;
    for (int v = v0; v < ve; v++) {
        float h = g_h2[(size_t)v * FD + f];
        s += h; q += h * h;
    }
    atomicAdd(&g_bns[f], (double)s);
    atomicAdd(&g_bns[CN + f], (double)q);
}

__global__ void __launch_bounds__(64) kD(int l, const float* __restrict__ gam,
                                         const float* __restrict__ bet) {
    int f = threadIdx.x;
    if (f < FD) {
        double mu = g_bns[f] / (double)NN;
        double var = g_bns[CN + f] / (double)NN - mu * mu;
        if (var < 0.0) var = 0.0;
        double rs = 1.0 / sqrt(var + 1e-5);
        float sc = (float)rs * gam[l * FD + f];
        g_scale[f] = sc;
        g_shift[f] = bet[l * FD + f] - (float)mu * sc;
    }
}

__global__ void __launch_bounds__(256) kE() {
    int idx = blockIdx.x * 256 + threadIdx.x;
    if (idx < NN * FD) {
        int v = idx / FD;
        int f = idx - v * FD;
        float h = g_h2[idx] * g_scale[f] + g_shift[f];
        g_h[idx] = fmaxf(h, 0.f);
    }
}

// ---------------- readout ----------------
__global__ void __launch_bounds__(256) k_zero_g() {
    int i = blockIdx.x * 256 + threadIdx.x;
    if (i < NG * FD) g_gr[i] = 0.f;
}

__global__ void __launch_bounds__(64) kF(const int* __restrict__ batch) {
    int f = threadIdx.x;
    int v0 = blockIdx.x * 256;
    int vend = min(v0 + 256, NN);
    float acc = 0.f;
    int cur = batch[v0];
    for (int v = v0; v < vend; v++) {
        int b = batch[v];
        if (b != cur) {
            if (f < FD) atomicAdd(&g_gr[cur * FD + f], acc);
            acc = 0.f;
            cur = b;
        }
        if (f < FD) acc += g_h[(size_t)v * FD + f];
    }
    if (f < FD) atomicAdd(&g_gr[cur * FD + f], acc);
}

__global__ void __launch_bounds__(32) kG(const float* __restrict__ W1,
                                         const float* __restrict__ b1,
                                         const float* __restrict__ W2,
                                         const float* __restrict__ b2,
                                         float* __restrict__ out) {
    int gid = blockIdx.x, j = threadIdx.x;
    float p = 0.f;
    if (j < 25) {
        float h = b1[j];
        #pragma unroll 10
        for (int ff = 0; ff < FD; ff++) h += g_gr[gid * FD + ff] * W1[ff * 25 + j];
        h = fmaxf(h, 0.f);
        p = h * W2[j];
    }
    for (int o = 16; o; o >>= 1) p += __shfl_down_sync(0xffffffffu, p, o);
    if (j == 0) out[gid] = p + b2[0];
}

// ---------------- launch ----------------
extern "C" void kernel_launch(void* const* d_in, const int* in_sizes, int n_in,
                              void* d_out, int out_size) {
    const float* x     = (const float*)d_in[0];
    const int*   ei    = (const int*)d_in[1];
    const int*   batch = (const int*)d_in[2];
    const float* Wg    = (const float*)d_in[3];
    const float* bg    = (const float*)d_in[4];
    const float* preW  = (const float*)d_in[5];
    const float* preb  = (const float*)d_in[6];
    const float* postW = (const float*)d_in[7];
    const float* linW  = (const float*)d_in[9];
    const float* gam   = (const float*)d_in[11];
    const float* bet   = (const float*)d_in[12];
    const float* W1    = (const float*)d_in[13];
    const float* b1    = (const float*)d_in[14];
    const float* W2    = (const float*)d_in[15];
    const float* b2    = (const float*)d_in[16];
    float* out = (float*)d_out;

    const int* srcp = ei;
    const int* dstp = ei + NE;

    k_zero0<<<(NN + 255) / 256, 256>>>();
    k_hist<<<(NE + 255) / 256, 256>>>(dstp);
    k_scan<<<1, SCAN_T>>>();
    // DUMMY launch #4: lands on ncu's fixed capture slot so we finally profile the
    // GEMM. Reads g_ext/g_C (same addresses as real runs), writes g_h2 which is
    // fully overwritten by the real kC before any consumer -> output unaffected.
    kC_mma<<<(NN + 127) / 128, 256>>>(0);
    k_dinv<<<(NN + 255) / 256, 256>>>();
    k_scatter<<<(NE + 255) / 256, 256>>>(srcp, dstp);
    k_amp<<<(NN + 255) / 256, 256>>>();
    k_gcnagg<<<(NN + 255) / 256, 256>>>(x);
    k_gcnmm<<<(NN * FD + 255) / 256, 256>>>(Wg, bg);
    k_combW<<<(NL * CN * KPP + 255) / 256, 256>>>(postW, linW);

    for (int l = 0; l < NL; l++) {
        kA<<<NN / 4, 256>>>(l, preW, preb);
        kB<<<NN / 4, 256>>>();
        k_zero_bn<<<1, 128>>>();
        kC_mma<<<(NN + 127) / 128, 256>>>(l);
        k_bnstat<<<(NN + 255) / 256, 64>>>();
        kD<<<1, 64>>>(l, gam, bet);
        kE<<<(NN * FD + 255) / 256, 256>>>();
    }

    k_zero_g<<<(NG * FD + 255) / 256, 256>>>();
    kF<<<(NN + 255) / 256, 64>>>(batch);
    kG<<<NG, 32>>>(W1, b1, W2, b2, out);
}

// round 17
// speedup vs baseline: 1.0646x; 1.0646x over previous
#include <cuda_runtime.h>
#include <cuda_bf16.h>
#include <math.h>
#include <stdint.h>

#define NN 100000
#define NE 1600000
#define NG 64
#define FD 50
#define KA 256        // compressed ext width: [h(50) | mean mn mx sd (200) | pad(6)]
#define NB 192        // GEMM N: 3 blocks of 64
#define NL 3
#define ASTR 40       // smem row stride in bf16 (32 + 8 pad)
#define MT 64         // rows per kC CTA

// ---------------- static scratch ----------------
__device__ int    g_deg[NN];
__device__ int    g_rowptr[NN + 1];
__device__ int    g_cursor[NN];
__device__ int    g_col[NE];
__device__ float  g_dinv[NN];
__device__ float  g_amp[NN];
__device__ float  g_att[NN];
__device__ double g_avg;
__device__ float  g_ax[2 * NN];
__device__ float  g_h[NN * FD];
__device__ float  g_h2[NN * FD];
__device__ float  g_base[NN * FD];
__device__ float  g_y[NN * FD];
__device__ __align__(16) __nv_bfloat16 g_extH[(size_t)NN * KA];  // ~51MB
__device__ __align__(16) __nv_bfloat16 g_extL[(size_t)NN * KA];  // ~51MB
__device__ __align__(16) __nv_bfloat16 g_CH[NL * NB * KA];
__device__ __align__(16) __nv_bfloat16 g_CL[NL * NB * KA];
__device__ double g_bns[2 * 64];
__device__ float  g_scale[64];
__device__ float  g_shift[64];
__device__ float  g_gr[NG * FD];

// ---------------- helpers ----------------
__device__ __forceinline__ uint32_t smem_u32(const void* p) {
    uint32_t a;
    asm("{ .reg .u64 t; cvta.to.shared.u64 t, %1; cvt.u32.u64 %0, t; }" : "=r"(a) : "l"(p));
    return a;
}
__device__ __forceinline__ void ldsm4(uint32_t* r, uint32_t a) {
    asm volatile("ldmatrix.sync.aligned.m8n8.x4.shared.b16 {%0,%1,%2,%3}, [%4];"
        : "=r"(r[0]), "=r"(r[1]), "=r"(r[2]), "=r"(r[3]) : "r"(a));
}
__device__ __forceinline__ void mma_bf16(float* d, const uint32_t* a, const uint32_t* b) {
    asm volatile("mma.sync.aligned.m16n8k16.row.col.f32.bf16.bf16.f32 "
        "{%0,%1,%2,%3}, {%4,%5,%6,%7}, {%8,%9}, {%0,%1,%2,%3};"
        : "+f"(d[0]), "+f"(d[1]), "+f"(d[2]), "+f"(d[3])
        : "r"(a[0]), "r"(a[1]), "r"(a[2]), "r"(a[3]), "r"(b[0]), "r"(b[1]));
}
__device__ __forceinline__ void bsplit(float v, __nv_bfloat16* H, __nv_bfloat16* L, size_t i) {
    __nv_bfloat16 h = __float2bfloat16(v);
    H[i] = h;
    L[i] = __float2bfloat16(v - __bfloat162float(h));
}
__device__ __forceinline__ void cpa16(uint32_t dst, const void* src, int sz) {
    asm volatile("cp.async.cg.shared.global [%0], [%1], 16, %2;"
        :: "r"(dst), "l"(src), "r"(sz) : "memory");
}
#define CP_COMMIT() asm volatile("cp.async.commit_group;" ::: "memory")
#define CP_WAIT1()  asm volatile("cp.async.wait_group 1;" ::: "memory")
#define CP_WAIT0()  asm volatile("cp.async.wait_group 0;" ::: "memory")

// ---------------- setup kernels ----------------
__global__ void __launch_bounds__(256) k_zero0() {
    int i = blockIdx.x * 256 + threadIdx.x;
    if (i < NN) g_deg[i] = 0;
    if (i == 0) g_avg = 0.0;
}

__global__ void __launch_bounds__(256) k_hist(const int* __restrict__ dst) {
    int e = blockIdx.x * 256 + threadIdx.x;
    if (e < NE) atomicAdd(&g_deg[dst[e]], 1);
}

#define SCAN_T 1024
#define SCAN_CHUNK 98
__global__ void __launch_bounds__(SCAN_T) k_scan() {
    __shared__ int part[SCAN_T];
    int t = threadIdx.x;
    int st = t * SCAN_CHUNK;
    int s = 0;
    for (int i = 0; i < SCAN_CHUNK; i++) {
        int idx = st + i;
        if (idx < NN) s += g_deg[idx];
    }
    part[t] = s;
    __syncthreads();
    for (int off = 1; off < SCAN_T; off <<= 1) {
        int v = 0;
        if (t >= off) v = part[t - off];
        __syncthreads();
        part[t] += v;
        __syncthreads();
    }
    int run = part[t] - s;
    for (int i = 0; i < SCAN_CHUNK; i++) {
        int idx = st + i;
        if (idx < NN) { g_rowptr[idx] = run; run += g_deg[idx]; }
    }
    if (t == SCAN_T - 1) g_rowptr[NN] = part[SCAN_T - 1];
}

__global__ void __launch_bounds__(256) k_dinv() {
    int v = blockIdx.x * 256 + threadIdx.x;
    float lg = 0.f;
    if (v < NN) {
        int d = g_deg[v];
        g_dinv[v] = rsqrtf((float)(d + 1));
        g_cursor[v] = g_rowptr[v];
        lg = log1pf((float)d);
    }
    for (int o = 16; o; o >>= 1) lg += __shfl_down_sync(0xffffffffu, lg, o);
    __shared__ float ws[8];
    int w = threadIdx.x >> 5, ln = threadIdx.x & 31;
    if (ln == 0) ws[w] = lg;
    __syncthreads();
    if (threadIdx.x == 0) {
        float tt = 0.f;
        for (int i = 0; i < 8; i++) tt += ws[i];
        atomicAdd(&g_avg, (double)tt);
    }
}

__global__ void __launch_bounds__(256) k_scatter(const int* __restrict__ src,
                                                 const int* __restrict__ dst) {
    int e = blockIdx.x * 256 + threadIdx.x;
    if (e < NE) {
        int d = dst[e];
        int p = atomicAdd(&g_cursor[d], 1);
        g_col[p] = src[e];
    }
}

__global__ void __launch_bounds__(256) k_amp() {
    int v = blockIdx.x * 256 + threadIdx.x;
    if (v < NN) {
        float avgl = (float)(g_avg / (double)NN);
        int d = g_deg[v];
        float dc = fmaxf((float)d, 1.f);
        float lg = log1pf(dc);
        g_amp[v] = lg / avgl;
        g_att[v] = avgl / lg;
    }
}

// GCN linearity: ax_v = dinv_v * (dinv_v*x_v + sum_u dinv_u*x_u); unroll-4 prefetch
__global__ void __launch_bounds__(256) k_gcnagg(const float* __restrict__ x) {
    int v = blockIdx.x * 256 + threadIdx.x;
    if (v >= NN) return;
    const float2* xv = (const float2*)x;
    int r0 = g_rowptr[v], r1 = g_rowptr[v + 1];
    float dv = g_dinv[v];
    float2 xs = xv[v];
    float a0 = dv * xs.x, a1 = dv * xs.y;
    int i = r0;
    for (; i + 4 <= r1; i += 4) {
        int u0 = g_col[i], u1 = g_col[i + 1], u2 = g_col[i + 2], u3 = g_col[i + 3];
        float d0 = g_dinv[u0], d1 = g_dinv[u1], d2 = g_dinv[u2], d3 = g_dinv[u3];
        float2 x0 = xv[u0], x1 = xv[u1], x2 = xv[u2], x3 = xv[u3];
        a0 += d0 * x0.x + d1 * x1.x + d2 * x2.x + d3 * x3.x;
        a1 += d0 * x0.y + d1 * x1.y + d2 * x2.y + d3 * x3.y;
    }
    for (; i < r1; i++) {
        int u = g_col[i];
        float du = g_dinv[u];
        float2 xu = xv[u];
        a0 += du * xu.x;
        a1 += du * xu.y;
    }
    g_ax[2 * v] = dv * a0;
    g_ax[2 * v + 1] = dv * a1;
}

__global__ void __launch_bounds__(256) k_gcnmm(const float* __restrict__ Wg,
                                               const float* __restrict__ bg) {
    int idx = blockIdx.x * 256 + threadIdx.x;
    if (idx < NN * FD) {
        int v = idx / FD;
        int f = idx - v * FD;
        g_h[idx] = g_ax[2 * v] * Wg[f] + g_ax[2 * v + 1] * Wg[FD + f] + bg[f];
    }
}

// ---------------- combined weights (rank-compressed, [l][blk*64+n][k]) ----------------
__global__ void __launch_bounds__(256) k_combW(const float* __restrict__ postW,
                                               const float* __restrict__ linW) {
    int idx = blockIdx.x * 256 + threadIdx.x;
    if (idx >= NL * NB * KA) return;
    int l = idx / (NB * KA);
    int r = idx - l * (NB * KA);
    int n2 = r / KA;
    int k = r - n2 * KA;
    int blk = n2 >> 6;
    int n = n2 & 63;
    float v = 0.f;
    int row = -1;
    if (k < FD) { if (blk == 0) row = k; }
    else if (k < 250) row = FD + blk * 200 + (k - FD);
    if (row >= 0 && n < FD) {
        const float* wq = postW + ((size_t)l * 650 + row) * FD;
        const float* wl = linW + (size_t)l * FD * FD;
        #pragma unroll 10
        for (int j = 0; j < FD; j++) v += wq[j] * wl[j * FD + n];
    }
    bsplit(v, g_CH, g_CL, idx);
}

// ---------------- per-layer kernels ----------------
__global__ void __launch_bounds__(256) kA(int l, const float* __restrict__ preW,
                                          const float* __restrict__ preb) {
    __shared__ float shW[100 * FD];
    __shared__ float shH[4][FD];
    int tid = threadIdx.x;
    const float* Wp = preW + (size_t)l * 100 * FD;
    for (int i = tid; i < 100 * FD; i += 256) shW[i] = Wp[i];
    int grp = tid >> 6, f = tid & 63;
    int v = blockIdx.x * 4 + grp;
    if (f < FD) shH[grp][f] = g_h[(size_t)v * FD + f];
    __syncthreads();
    if (f < FD) {
        float b = preb[l * FD + f];
        float yv = 0.f;
        #pragma unroll 10
        for (int k = 0; k < FD; k++) {
            float hv = shH[grp][k];
            b  += hv * shW[k * FD + f];
            yv += hv * shW[(FD + k) * FD + f];
        }
        g_base[(size_t)v * FD + f] = b;
        g_y[(size_t)v * FD + f] = yv;
    }
}

// kB: edge aggregation, unroll-4; writes COMPRESSED ext (250 + 6 pad cols) hi/lo
__global__ void __launch_bounds__(256) kB() {
    int tid = threadIdx.x;
    int grp = tid >> 6, f = tid & 63;
    int v = blockIdx.x * 4 + grp;
    __nv_bfloat16* eh = g_extH + (size_t)v * KA;
    __nv_bfloat16* el = g_extL + (size_t)v * KA;
    if (f >= FD) {
        int p = 250 + (f - FD);
        if (p < KA) {
            __nv_bfloat16 z = __float2bfloat16(0.f);
            eh[p] = z;
            el[p] = z;
        }
        return;
    }
    float base = g_base[(size_t)v * FD + f];
    int r0 = g_rowptr[v], r1 = g_rowptr[v + 1];
    float s = 0.f, ss = 0.f, mn = INFINITY, mx = -INFINITY;
    int i = r0;
    for (; i + 4 <= r1; i += 4) {
        int u0 = g_col[i], u1 = g_col[i + 1], u2 = g_col[i + 2], u3 = g_col[i + 3];
        float h0 = base + g_y[(size_t)u0 * FD + f];
        float h1 = base + g_y[(size_t)u1 * FD + f];
        float h2 = base + g_y[(size_t)u2 * FD + f];
        float h3 = base + g_y[(size_t)u3 * FD + f];
        s += (h0 + h1) + (h2 + h3);
        ss += (h0 * h0 + h1 * h1) + (h2 * h2 + h3 * h3);
        mn = fminf(mn, fminf(fminf(h0, h1), fminf(h2, h3)));
        mx = fmaxf(mx, fmaxf(fmaxf(h0, h1), fmaxf(h2, h3)));
    }
    for (; i < r1; i++) {
        int u = g_col[i];
        float h = base + g_y[(size_t)u * FD + f];
        s += h; ss += h * h;
        mn = fminf(mn, h); mx = fmaxf(mx, h);
    }
    int deg = r1 - r0;
    float dc = fmaxf((float)deg, 1.f);
    float mean = s / dc;
    float msq = ss / dc;
    float var = fmaxf(msq - mean * mean, 0.f);
    float sd = sqrtf(var + 1e-5f);
    if (deg == 0) { mn = 0.f; mx = 0.f; }
    bsplit(g_h[(size_t)v * FD + f], eh, el, f);
    bsplit(mean, eh, el, 50 + f);
    bsplit(mn,   eh, el, 100 + f);
    bsplit(mx,   eh, el, 150 + f);
    bsplit(sd,   eh, el, 200 + f);
}

__global__ void __launch_bounds__(128) k_zero_bn() {
    int i = threadIdx.x;
    if (i < 128) g_bns[i] = 0.0;
}

// ---------------- kC: cp.async-pipelined MMA + smem combine + fused BN ----------------
// 384 threads / 12 warps: wm(2) x blk(3) x wn(2); warp tile 32 rows x 32 cols of one block.
// Stage (bytes): sAh 5120 | sAl 5120 | sBh 15360 | sBl 15360 = 40960; x2 stages = 81920.
#define STG_B 40960
#define SMEM_KC (2 * STG_B)

__global__ void __launch_bounds__(384) kC_mma(int l) {
    extern __shared__ __align__(16) char dsm[];
    __shared__ float redS[64];
    __shared__ float redQ[64];
    int tid = threadIdx.x, lane = tid & 31, wid = tid >> 5;
    int wm = wid & 1;
    int t2 = wid >> 1;
    int blk = t2 >> 1, wn = t2 & 1;
    int v0 = blockIdx.x * MT;
    uint32_t sb = smem_u32(dsm);

    if (tid < 64) { redS[tid] = 0.f; redQ[tid] = 0.f; }

    const __nv_bfloat16* BHl = g_CH + (size_t)l * NB * KA;
    const __nv_bfloat16* BLl = g_CL + (size_t)l * NB * KA;

    // ---- staging lambda (macro-ish): chunk c into stage stg ----
    #define STAGE_CHUNK(c, stg) do {                                                  \
        int k0_ = (c) * 32;                                                           \
        uint32_t base_ = sb + (stg) * STG_B;                                          \
        for (int i_ = tid; i_ < 2048; i_ += 384) {                                    \
            if (i_ < 512) {                                                           \
                int a_ = i_ & 255;                                                    \
                int rl_ = a_ >> 2, q_ = a_ & 3;                                       \
                int v_ = v0 + rl_;                                                    \
                int sz_ = (v_ < NN) ? 16 : 0;                                         \
                int vc_ = (v_ < NN) ? v_ : (NN - 1);                                  \
                const __nv_bfloat16* s_ = ((i_ < 256) ? g_extH : g_extL)              \
                                          + (size_t)vc_ * KA + k0_ + q_ * 8;          \
                uint32_t d_ = base_ + ((i_ < 256) ? 0 : 5120) + rl_ * 80 + q_ * 16;   \
                cpa16(d_, s_, sz_);                                                   \
            } else {                                                                  \
                int b_ = i_ - 512;                                                    \
                int hi_ = (b_ < 768);                                                 \
                int j_ = hi_ ? b_ : (b_ - 768);                                       \
                int rw_ = j_ >> 2, q_ = j_ & 3;                                       \
                const __nv_bfloat16* s_ = (hi_ ? BHl : BLl)                           \
                                          + (size_t)rw_ * KA + k0_ + q_ * 8;          \
                uint32_t d_ = base_ + 10240 + (hi_ ? 0 : 15360) + rw_ * 80 + q_ * 16; \
                cpa16(d_, s_, 16);                                                    \
            }                                                                         \
        }                                                                             \
    } while (0)

    float acc[2][4][4] = {};
    int lr = lane & 15, lh = lane >> 4;
    int bgrp = lane >> 3, bli = lane & 7;

    STAGE_CHUNK(0, 0);
    CP_COMMIT();

    for (int c = 0; c < KA / 32; c++) {
        int stg = c & 1;
        if (c + 1 < KA / 32) {
            STAGE_CHUNK(c + 1, (c + 1) & 1);
            CP_COMMIT();
            CP_WAIT1();
        } else {
            CP_WAIT0();
        }
        __syncthreads();

        uint32_t aB = sb + stg * STG_B;
        uint32_t bB = aB + 10240;
        #pragma unroll
        for (int kk = 0; kk < 2; kk++) {
            uint32_t ah[2][4], al[2][4], bh[4][2], bl[4][2];
            #pragma unroll
            for (int im = 0; im < 2; im++) {
                uint32_t off = (uint32_t)(((wm * 32 + im * 16 + lr) * ASTR + kk * 16 + lh * 8) * 2);
                ldsm4(ah[im], aB + off);
                ldsm4(al[im], aB + 5120 + off);
            }
            #pragma unroll
            for (int jg = 0; jg < 2; jg++) {
                uint32_t off = (uint32_t)(((blk * 64 + wn * 32 + jg * 16 + (bgrp >> 1) * 8 + bli) * ASTR
                                           + kk * 16 + (bgrp & 1) * 8) * 2);
                uint32_t r4[4];
                ldsm4(r4, bB + off);
                bh[jg * 2][0] = r4[0]; bh[jg * 2][1] = r4[1];
                bh[jg * 2 + 1][0] = r4[2]; bh[jg * 2 + 1][1] = r4[3];
                ldsm4(r4, bB + 15360 + off);
                bl[jg * 2][0] = r4[0]; bl[jg * 2][1] = r4[1];
                bl[jg * 2 + 1][0] = r4[2]; bl[jg * 2 + 1][1] = r4[3];
            }
            #pragma unroll
            for (int im = 0; im < 2; im++)
                #pragma unroll
                for (int jn = 0; jn < 4; jn++) {
                    mma_bf16(acc[im][jn], ah[im], bh[jn]);
                    mma_bf16(acc[im][jn], ah[im], bl[jn]);
                    mma_bf16(acc[im][jn], al[im], bh[jn]);
                }
        }
        __syncthreads();   // protect stage buffer reuse
    }

    // ---- epilogue: cross-block combine via smem scratch (reuse stage buffers) ----
    float* scr = (float*)dsm;   // 64 rows x 192 cols, stride 192 (49152 B <= 81920)
    #pragma unroll
    for (int im = 0; im < 2; im++) {
        int ra = wm * 32 + im * 16 + (lane >> 2);
        #pragma unroll
        for (int jn = 0; jn < 4; jn++) {
            int cb = blk * 64 + wn * 32 + jn * 8 + (lane & 3) * 2;
            scr[ra * NB + cb] = acc[im][jn][0];
            scr[ra * NB + cb + 1] = acc[im][jn][1];
            scr[(ra + 8) * NB + cb] = acc[im][jn][2];
            scr[(ra + 8) * NB + cb + 1] = acc[im][jn][3];
        }
    }
    __syncthreads();

    for (int idx = tid; idx < MT * FD; idx += 384) {
        int r = idx / FD, cc = idx - r * FD;
        int v = v0 + r;
        if (v < NN) {
            float o = scr[r * NB + cc]
                    + g_amp[v] * scr[r * NB + 64 + cc]
                    + g_att[v] * scr[r * NB + 128 + cc];
            g_h2[(size_t)v * FD + cc] = o;
            atomicAdd(&redS[cc], o);
            atomicAdd(&redQ[cc], o * o);
        }
    }
    __syncthreads();
    if (tid < FD) {
        atomicAdd(&g_bns[tid], (double)redS[tid]);
        atomicAdd(&g_bns[64 + tid], (double)redQ[tid]);
    }
    #undef STAGE_CHUNK
}

__global__ void __launch_bounds__(64) kD(int l, const float* __restrict__ gam,
                                         const float* __restrict__ bet) {
    int f = threadIdx.x;
    if (f < FD) {
        double mu = g_bns[f] / (double)NN;
        double var = g_bns[64 + f] / (double)NN - mu * mu;
        if (var < 0.0) var = 0.0;
        double rs = 1.0 / sqrt(var + 1e-5);
        float sc = (float)rs * gam[l * FD + f];
        g_scale[f] = sc;
        g_shift[f] = bet[l * FD + f] - (float)mu * sc;
    }
}

__global__ void __launch_bounds__(256) kE() {
    int idx = blockIdx.x * 256 + threadIdx.x;
    if (idx < NN * FD) {
        int v = idx / FD;
        int f = idx - v * FD;
        float h = g_h2[idx] * g_scale[f] + g_shift[f];
        g_h[idx] = fmaxf(h, 0.f);
    }
}

// ---------------- readout ----------------
__global__ void __launch_bounds__(256) k_zero_g() {
    int i = blockIdx.x * 256 + threadIdx.x;
    if (i < NG * FD) g_gr[i] = 0.f;
}

__global__ void __launch_bounds__(64) kF(const int* __restrict__ batch) {
    int f = threadIdx.x;
    int v0 = blockIdx.x * 256;
    int vend = min(v0 + 256, NN);
    float acc = 0.f;
    int cur = batch[v0];
    for (int v = v0; v < vend; v++) {
        int b = batch[v];
        if (b != cur) {
            if (f < FD) atomicAdd(&g_gr[cur * FD + f], acc);
            acc = 0.f;
            cur = b;
        }
        if (f < FD) acc += g_h[(size_t)v * FD + f];
    }
    if (f < FD) atomicAdd(&g_gr[cur * FD + f], acc);
}

__global__ void __launch_bounds__(32) kG(const float* __restrict__ W1,
                                         const float* __restrict__ b1,
                                         const float* __restrict__ W2,
                                         const float* __restrict__ b2,
                                         float* __restrict__ out) {
    int gid = blockIdx.x, j = threadIdx.x;
    float p = 0.f;
    if (j < 25) {
        float h = b1[j];
        #pragma unroll 10
        for (int ff = 0; ff < FD; ff++) h += g_gr[gid * FD + ff] * W1[ff * 25 + j];
        h = fmaxf(h, 0.f);
        p = h * W2[j];
    }
    for (int o = 16; o; o >>= 1) p += __shfl_down_sync(0xffffffffu, p, o);
    if (j == 0) out[gid] = p + b2[0];
}

// ---------------- launch ----------------
extern "C" void kernel_launch(void* const* d_in, const int* in_sizes, int n_in,
                              void* d_out, int out_size) {
    const float* x     = (const float*)d_in[0];
    const int*   ei    = (const int*)d_in[1];
    const int*   batch = (const int*)d_in[2];
    const float* Wg    = (const float*)d_in[3];
    const float* bg    = (const float*)d_in[4];
    const float* preW  = (const float*)d_in[5];
    const float* preb  = (const float*)d_in[6];
    const float* postW = (const float*)d_in[7];
    const float* linW  = (const float*)d_in[9];
    const float* gam   = (const float*)d_in[11];
    const float* bet   = (const float*)d_in[12];
    const float* W1    = (const float*)d_in[13];
    const float* b1    = (const float*)d_in[14];
    const float* W2    = (const float*)d_in[15];
    const float* b2    = (const float*)d_in[16];
    float* out = (float*)d_out;

    const int* srcp = ei;
    const int* dstp = ei + NE;

    static int attr_set = 0;
    if (!attr_set) {
        cudaFuncSetAttribute(kC_mma, cudaFuncAttributeMaxDynamicSharedMemorySize, SMEM_KC);
        attr_set = 1;
    }

    int kc_grid = (NN + MT - 1) / MT;

    k_zero0<<<(NN + 255) / 256, 256>>>();
    k_hist<<<(NE + 255) / 256, 256>>>(dstp);
    k_scan<<<1, SCAN_T>>>();
    // DUMMY launch #4: lands on ncu's fixed capture slot -> profiles the new kC.
    // Writes g_h2 (fully overwritten by real layer-0 kC) and g_bns (zeroed by
    // k_zero_bn before the real kC) -> output unaffected, deterministic.
    kC_mma<<<kc_grid, 384, SMEM_KC>>>(0);
    k_dinv<<<(NN + 255) / 256, 256>>>();
    k_scatter<<<(NE + 255) / 256, 256>>>(srcp, dstp);
    k_amp<<<(NN + 255) / 256, 256>>>();
    k_gcnagg<<<(NN + 255) / 256, 256>>>(x);
    k_gcnmm<<<(NN * FD + 255) / 256, 256>>>(Wg, bg);
    k_combW<<<(NL * NB * KA + 255) / 256, 256>>>(postW, linW);

    for (int l = 0; l < NL; l++) {
        kA<<<NN / 4, 256>>>(l, preW, preb);
        kB<<<NN / 4, 256>>>();
        k_zero_bn<<<1, 128>>>();
        kC_mma<<<kc_grid, 384, SMEM_KC>>>(l);
        kD<<<1, 64>>>(l, gam, bet);
        kE<<<(NN * FD + 255) / 256, 256>>>();
    }

    k_zero_g<<<(NG * FD + 255) / 256, 256>>>();
    kF<<<(NN + 255) / 256, 64>>>(batch);
    kG<<<NG, 32>>>(W1, b1, W2, b2, out);
}